// round 16
// baseline (speedup 1.0000x reference)
#include <cuda_runtime.h>
#include <cuda_bf16.h>
#include <cuda_fp8.h>
#include <stdint.h>

// ---------------------------------------------------------------------------
// InfoNCELoss on GB300 (sm_103 legacy mma.sync path, FP8 e4m3 m16n8k32)
// R16 = R15 + issue-slot diet: precomputed ldsm offsets (ks=1 = ks=0 ^ 32),
//       fully unrolled kt loop (compile-time slot/phase). ncu R15 showed
//       issue flooded by address ALU (37% alu, tensor stuck at 59%).
// ---------------------------------------------------------------------------

#define DDIM 512
#define FP8_SCALE 32.0f

// fp8 matrices, TILED layout: [panel(128r)][kt(8)][r(128)][64B], swizzled chunks
__device__ __align__(1024) uint32_t g_Anq[(size_t)4096  * 128];
__device__ __align__(1024) uint32_t g_Pnq[(size_t)4096  * 128];
__device__ __align__(1024) uint32_t g_Nnq[(size_t)16384 * 128];
__device__ float    g_invA[4096];
__device__ float    g_invP[4096];
__device__ float    g_invN[16384];
__device__ float    g_S[4096];
__device__ int      g_done[64];      // per-64-row-panel neg completion counters
__device__ int      g_pos_done;
__device__ int      g_cs_done;
__device__ double   g_sum_loss;
__device__ double   g_cs[3][DDIM];

// ============================ PTX helpers ==================================
__device__ __forceinline__ uint32_t smem_to_u32(const void* p) {
    uint32_t a;
    asm("{ .reg .u64 t; cvta.to.shared.u64 t, %1; cvt.u32.u64 %0, t; }"
        : "=r"(a) : "l"(p));
    return a;
}
__device__ __forceinline__ void bulk_cp(uint32_t dst, const void* src,
                                        uint32_t bytes, uint32_t mbar) {
    asm volatile(
        "cp.async.bulk.shared::cta.global.mbarrier::complete_tx::bytes "
        "[%0], [%1], %2, [%3];"
        :: "r"(dst), "l"(src), "r"(bytes), "r"(mbar) : "memory");
}
#define MBARRIER_INIT(mbar, count) \
    asm volatile("mbarrier.init.shared.b64 [%0], %1;" \
        :: "r"((uint32_t)(mbar)), "r"((uint32_t)(count)) : "memory")
#define MBARRIER_EXPECT_TX(mbar, bytes) \
    asm volatile("mbarrier.arrive.expect_tx.shared.b64 _, [%0], %1;" \
        :: "r"((uint32_t)(mbar)), "r"((uint32_t)(bytes)) : "memory")
#define MBARRIER_WAIT_PARITY(mbar_smem_addr, phase_parity) do { \
    uint32_t _mbar = (uint32_t)(mbar_smem_addr); \
    uint32_t _parity = (uint32_t)(phase_parity); \
    uint32_t _done; \
    asm volatile( \
        "{\n\t.reg .pred p;\n\t" \
        "mbarrier.try_wait.parity.acquire.cta.shared::cta.b64 p, [%1], %2;\n\t" \
        "selp.b32 %0, 1, 0, p;\n\t}" \
        : "=r"(_done) : "r"(_mbar), "r"(_parity) : "memory"); \
    if (!_done) { \
        asm volatile( \
            "{\n\t.reg .pred P1;\n\t" \
            "WAIT_LOOP_%=:\n\t" \
            "mbarrier.try_wait.parity.acquire.cta.shared::cta.b64 P1, [%0], %1, 0x989680;\n\t" \
            "@P1 bra.uni WAIT_DONE_%=;\n\t" \
            "bra.uni WAIT_LOOP_%=;\n\t" \
            "WAIT_DONE_%=:\n\t}" \
            :: "r"(_mbar), "r"(_parity) : "memory"); \
    } \
} while (0)

__device__ __forceinline__ void ldsm_x4(uint32_t (&r)[4], uint32_t addr) {
    asm volatile("ldmatrix.sync.aligned.m8n8.x4.shared.b16 {%0,%1,%2,%3}, [%4];"
                 : "=r"(r[0]), "=r"(r[1]), "=r"(r[2]), "=r"(r[3]) : "r"(addr));
}
__device__ __forceinline__ void mma16832(float (&c)[4], const uint32_t (&a)[4],
                                         uint32_t b0, uint32_t b1) {
    asm volatile(
        "mma.sync.aligned.m16n8k32.row.col.f32.e4m3.e4m3.f32 "
        "{%0,%1,%2,%3}, {%4,%5,%6,%7}, {%8,%9}, {%0,%1,%2,%3};"
        : "+f"(c[0]), "+f"(c[1]), "+f"(c[2]), "+f"(c[3])
        : "r"(a[0]), "r"(a[1]), "r"(a[2]), "r"(a[3]), "r"(b0), "r"(b1));
}

// ====================== launch 1: normalize + zero =========================
#define NORM_BLOCKS 3072

__global__ void __launch_bounds__(256) normalize_kernel(const float* __restrict__ a,
                                                        const float* __restrict__ p,
                                                        const float* __restrict__ n) {
    if (blockIdx.x >= NORM_BLOCKS) {
        int i = (blockIdx.x - NORM_BLOCKS) * 256 + threadIdx.x;   // 0..4095
        g_S[i] = 0.0f;
        if (i < 3 * DDIM) ((double*)g_cs)[i] = 0.0;
        if (i < 64) g_done[i] = 0;
        if (i == 0) { g_sum_loss = 0.0; g_pos_done = 0; g_cs_done = 0; }
        return;
    }

    int rowBase;
    const float* in;
    uint32_t* outq;
    float* ginv;
    if (blockIdx.x < 512) {
        in = a; outq = g_Anq; ginv = g_invA; rowBase = blockIdx.x * 8;
    } else if (blockIdx.x < 1024) {
        in = p; outq = g_Pnq; ginv = g_invP; rowBase = (blockIdx.x - 512) * 8;
    } else {
        in = n; outq = g_Nnq; ginv = g_invN; rowBase = (blockIdx.x - 1024) * 8;
    }

    const int lane = threadIdx.x & 31;
    const int row = rowBase + (threadIdx.x >> 5);

    const float4* src = (const float4*)in + (size_t)row * (DDIM / 4);
    float4 v[4];
    #pragma unroll
    for (int i = 0; i < 4; i++) v[i] = src[lane + 32 * i];

    float ss = 0.0f;
    #pragma unroll
    for (int i = 0; i < 4; i++)
        ss += v[i].x * v[i].x + v[i].y * v[i].y + v[i].z * v[i].z + v[i].w * v[i].w;
    #pragma unroll
    for (int off = 16; off; off >>= 1)
        ss += __shfl_xor_sync(0xffffffffu, ss, off);

    float inv = 1.0f / fmaxf(sqrtf(ss), 1e-12f);
    if (lane == 0) ginv[row] = inv;

    const float sc = inv * FP8_SCALE;
    const uint32_t r = (uint32_t)row & 127;
    const uint32_t panel = (uint32_t)row >> 7;
    uint32_t* orow = outq + (size_t)panel * 16384 + r * 16;

    #pragma unroll
    for (int i = 0; i < 4; i++) {
        __nv_fp8x2_storage_t lo = __nv_cvt_float2_to_fp8x2(
            make_float2(v[i].x * sc, v[i].y * sc), __NV_SATFINITE, __NV_E4M3);
        __nv_fp8x2_storage_t hi = __nv_cvt_float2_to_fp8x2(
            make_float2(v[i].z * sc, v[i].w * sc), __NV_SATFINITE, __NV_E4M3);
        uint32_t packed = (uint32_t)lo | ((uint32_t)hi << 16);

        uint32_t t = (uint32_t)(lane + 32 * i);
        uint32_t kt = t >> 4;
        uint32_t cc = (t >> 2) & 3;
        uint32_t w = t & 3;
        uint32_t sw = cc ^ ((r >> 1) & 3);
        orow[kt * 2048 + sw * 4 + w] = packed;
    }
}

// ================= launch 2: GEMMs + colsum + finalize =====================
// CTA tile 64(M) x 128(N), warp tile 32x64, 128 threads, 4 CTAs/SM.
// bid [0,8192):        NEG  (panel64 = bid>>7, col = bid&127)   B = g_Nnq
// bid [8192,10240):    POS  (panel64 = b2>>5,  col = b2&31)     B = g_Pnq
// bid [10240,10624):   COLSUM
// bid 10624:           FINALIZE
#define A_STAGE 4096
#define STAGE_BYTES 12288
#define NEG_CTAS 8192
#define POS_CTAS 2048
#define GEMM_CTAS (NEG_CTAS + POS_CTAS)
#define CS_BLOCKS 384
#define FIN_BID (GEMM_CTAS + CS_BLOCKS)

__global__ void __launch_bounds__(128, 4) mma_fused_kernel(
        const float* __restrict__ inA, const float* __restrict__ inP,
        const float* __restrict__ inN, float* __restrict__ out,
        int B, int P, int N) {
    __shared__ __align__(128) char sbuf[3 * STAGE_BYTES];   // 36KB
    __shared__ __align__(8) uint64_t mbars[3];

    const int tid = threadIdx.x;
    const int bid = blockIdx.x;
    const int lane = tid & 31;
    const int warp = tid >> 5;

    // ---------------- finalize block ----------------
    if (bid == FIN_BID) {
        if (tid == 0) {
            while (((volatile int*)&g_pos_done)[0] < POS_CTAS ||
                   ((volatile int*)&g_cs_done)[0] < CS_BLOCKS)
                __nanosleep(128);
        }
        __syncthreads();
        __threadfence();

        double dAP = 0.0, dAN = 0.0;
        #pragma unroll
        for (int j = 0; j < 4; j++) {
            int col = tid + j * 128;
            double csA = __ldcg(&g_cs[0][col]);
            dAP += csA * __ldcg(&g_cs[1][col]);
            dAN += csA * __ldcg(&g_cs[2][col]);
        }
        #pragma unroll
        for (int off = 16; off; off >>= 1) {
            dAP += __shfl_xor_sync(0xffffffffu, dAP, off);
            dAN += __shfl_xor_sync(0xffffffffu, dAN, off);
        }
        __shared__ double rB[4], rC[4];
        if (lane == 0) { rB[warp] = dAP; rC[warp] = dAN; }
        __syncthreads();
        if (tid == 0) {
            double sAP = rB[0] + rB[1] + rB[2] + rB[3];
            double sAN = rC[0] + rC[1] + rC[2] + rC[3];
            const double T = 0.07;
            double bp = (double)B * (double)P;
            double bn = (double)B * (double)N;
            double mp = sAP / (bp * T);
            double mn = sAN / (bn * T);
            double tl = __ldcg(&g_sum_loss) / bp;
            out[0] = (float)tl;
            out[1] = (float)mp;
            out[2] = (float)mn;
            out[3] = (float)(mp - mn);
        }
        return;
    }

    // ---------------- colsum blocks ----------------
    if (bid >= GEMM_CTAS) {
        int b3 = bid - GEMM_CTAS;
        const float* in;
        const float* ginv;
        int m, base;
        if (b3 < 64)        { in = inA; ginv = g_invA; m = 0; base = b3 * 64; }
        else if (b3 < 128)  { in = inP; ginv = g_invP; m = 1; base = (b3 - 64) * 64; }
        else                { in = inN; ginv = g_invN; m = 2; base = (b3 - 128) * 64; }

        float acc[4] = {0.0f, 0.0f, 0.0f, 0.0f};
        for (int r = 0; r < 64; r++) {
            float iv = ginv[base + r];
            const float* rowp = in + (size_t)(base + r) * DDIM;
            #pragma unroll
            for (int j = 0; j < 4; j++)
                acc[j] += rowp[tid + j * 128] * iv;
        }
        #pragma unroll
        for (int j = 0; j < 4; j++)
            atomicAdd(&g_cs[m][tid + j * 128], (double)acc[j]);

        __syncthreads();
        if (tid == 0) {
            __threadfence();
            atomicAdd(&g_cs_done, 1);
        }
        return;
    }

    // ---------------- GEMM blocks ----------------
    const uint32_t sb = smem_to_u32(sbuf);
    const uint32_t mb = smem_to_u32(mbars);
    const int m0 = (warp >> 1) * 32;     // 0 or 32 within the 64-row tile
    const int n0 = (warp & 1) * 64;      // 0 or 64 within the 128-col tile

    const bool isNeg = (bid < NEG_CTAS);
    int rowPanel, colIdx;                // rowPanel in 64-row units
    const char* gB;
    if (isNeg) {
        rowPanel = bid >> 7;
        colIdx = bid & 127;
        gB = (const char*)g_Nnq + (size_t)colIdx * 65536;
    } else {
        int b2 = bid - NEG_CTAS;
        rowPanel = b2 >> 5;
        colIdx = b2 & 31;
        gB = (const char*)g_Pnq + (size_t)colIdx * 65536;
    }
    const int rowBase = rowPanel * 64;
    const char* gA = (const char*)g_Anq + (size_t)(rowPanel >> 1) * 65536
                     + (size_t)(rowPanel & 1) * 4096;

    float c[2][8][4];
    #pragma unroll
    for (int i = 0; i < 2; i++)
        #pragma unroll
        for (int j = 0; j < 8; j++)
            #pragma unroll
            for (int e = 0; e < 4; e++) c[i][j][e] = 0.0f;

    if (tid == 0) {
        #pragma unroll
        for (int s = 0; s < 3; s++) MBARRIER_INIT(mb + s * 8, 1);
    }
    __syncthreads();

    if (tid == 0) {
        #pragma unroll
        for (int s = 0; s < 3; s++) {
            MBARRIER_EXPECT_TX(mb + s * 8, STAGE_BYTES);
            bulk_cp(sb + s * STAGE_BYTES,           gA + (size_t)s * 8192, 4096, mb + s * 8);
            bulk_cp(sb + s * STAGE_BYTES + A_STAGE, gB + (size_t)s * 8192, 8192, mb + s * 8);
        }
    }

    // ---- precomputed ldsm offsets (ks=0); ks=1 address = ks=0 ^ 32 ----
    uint32_t offA[2], offB[4];
    #pragma unroll
    for (int mf = 0; mf < 2; mf++) {
        uint32_t r = m0 + mf * 16 + (lane & 15);
        uint32_t cc = (lane >> 4);                       // ks=0: cc in {0,1}
        offA[mf] = (r * 4 + (cc ^ ((r >> 1) & 3))) * 16;
    }
    #pragma unroll
    for (int np = 0; np < 4; np++) {
        uint32_t grp = lane >> 3;
        uint32_t n = n0 + np * 16 + ((grp >> 1) ? 8 : 0) + (lane & 7);
        uint32_t cc = (grp & 1);                         // ks=0: cc in {0,1}
        offB[np] = A_STAGE + (n * 4 + (cc ^ ((n >> 1) & 3))) * 16;
    }

    uint32_t a2[2][4], b2[4][4];

    #pragma unroll
    for (int kt = 0; kt < 8; kt++) {
        const int slot = kt % 3;                         // compile-time now
        const uint32_t stBase = sb + slot * STAGE_BYTES;
        MBARRIER_WAIT_PARITY(mb + slot * 8, (kt / 3) & 1);

        #pragma unroll
        for (int ks = 0; ks < 2; ks++) {
            const uint32_t x = ks * 32;                  // swizzle-compatible k-step
            ldsm_x4(a2[0], stBase + (offA[0] ^ x));
            ldsm_x4(a2[1], stBase + (offA[1] ^ x));
            ldsm_x4(b2[0], stBase + (offB[0] ^ x));
            ldsm_x4(b2[1], stBase + (offB[1] ^ x));
            ldsm_x4(b2[2], stBase + (offB[2] ^ x));
            ldsm_x4(b2[3], stBase + (offB[3] ^ x));
            #pragma unroll
            for (int mf = 0; mf < 2; mf++)
                #pragma unroll
                for (int nf = 0; nf < 8; nf++)
                    mma16832(c[mf][nf], a2[mf],
                             b2[nf >> 1][(nf & 1) * 2], b2[nf >> 1][(nf & 1) * 2 + 1]);
        }

        __syncthreads();
        if (tid == 0 && kt + 3 < 8) {
            const int nt = kt + 3;
            MBARRIER_EXPECT_TX(mb + slot * 8, STAGE_BYTES);
            bulk_cp(sb + slot * STAGE_BYTES,           gA + (size_t)nt * 8192, 4096, mb + slot * 8);
            bulk_cp(sb + slot * STAGE_BYTES + A_STAGE, gB + (size_t)nt * 8192, 8192, mb + slot * 8);
        }
    }

    // ---- fused epilogues (accumulator = SCALE^2 * dot) ----
    const float invT = 1.0f / (0.07f * FP8_SCALE * FP8_SCALE);
    const int gID = lane >> 2;

    if (isNeg) {
        #pragma unroll
        for (int mf = 0; mf < 2; mf++) {
            float rs0 = 0.0f, rs1 = 0.0f;
            #pragma unroll
            for (int nf = 0; nf < 8; nf++) {
                rs0 += __expf(c[mf][nf][0] * invT) + __expf(c[mf][nf][1] * invT);
                rs1 += __expf(c[mf][nf][2] * invT) + __expf(c[mf][nf][3] * invT);
            }
            rs0 += __shfl_xor_sync(0xffffffffu, rs0, 1);
            rs0 += __shfl_xor_sync(0xffffffffu, rs0, 2);
            rs1 += __shfl_xor_sync(0xffffffffu, rs1, 1);
            rs1 += __shfl_xor_sync(0xffffffffu, rs1, 2);
            if ((lane & 3) == 0) {
                int row = rowBase + m0 + mf * 16 + gID;
                atomicAdd(&g_S[row], rs0);
                atomicAdd(&g_S[row + 8], rs1);
            }
        }
        __syncthreads();
        if (tid == 0) {
            __threadfence();
            atomicAdd(&g_done[rowPanel], 1);
        }
    } else {
        if (tid == 0) {
            while (((volatile int*)g_done)[rowPanel] < 128)
                __nanosleep(64);
        }
        __syncthreads();
        __threadfence();

        float lsum = 0.0f;
        #pragma unroll
        for (int mf = 0; mf < 2; mf++) {
            int row = rowBase + m0 + mf * 16 + gID;
            float S0 = __ldcg(&g_S[row]);
            float S1 = __ldcg(&g_S[row + 8]);
            #pragma unroll
            for (int nf = 0; nf < 8; nf++) {
                float p0 = __expf(c[mf][nf][0] * invT);
                float p1 = __expf(c[mf][nf][1] * invT);
                float p2 = __expf(c[mf][nf][2] * invT);
                float p3 = __expf(c[mf][nf][3] * invT);
                lsum += __logf(__fdividef(p0, p0 + S0) + 1e-8f);
                lsum += __logf(__fdividef(p1, p1 + S0) + 1e-8f);
                lsum += __logf(__fdividef(p2, p2 + S1) + 1e-8f);
                lsum += __logf(__fdividef(p3, p3 + S1) + 1e-8f);
            }
        }
        double acc = -(double)lsum;
        #pragma unroll
        for (int off = 16; off; off >>= 1)
            acc += __shfl_xor_sync(0xffffffffu, acc, off);
        __shared__ double red[4];
        if (lane == 0) red[warp] = acc;
        __syncthreads();
        if (tid == 0) {
            atomicAdd(&g_sum_loss, red[0] + red[1] + red[2] + red[3]);
            __threadfence();
            atomicAdd(&g_pos_done, 1);
        }
    }
}

// ============================ launch =======================================
extern "C" void kernel_launch(void* const* d_in, const int* in_sizes, int n_in,
                              void* d_out, int out_size) {
    const float* a = (const float*)d_in[0];
    const float* p = (const float*)d_in[1];
    const float* n = (const float*)d_in[2];
    int B = in_sizes[0] / DDIM;   // 4096
    int P = in_sizes[1] / DDIM;   // 4096
    int N = in_sizes[2] / DDIM;   // 16384

    normalize_kernel<<<NORM_BLOCKS + 16, 256>>>(a, p, n);
    mma_fused_kernel<<<FIN_BID + 1, 128>>>(a, p, n, (float*)d_out, B, P, N);
}

// round 17
// speedup vs baseline: 1.0925x; 1.0925x over previous
#include <cuda_runtime.h>
#include <cuda_bf16.h>
#include <cuda_fp8.h>
#include <stdint.h>

// ---------------------------------------------------------------------------
// InfoNCELoss on GB300 (sm_103 legacy mma.sync path, FP8 e4m3 m16n8k32)
// R17 = R15 base (best known, 243.3us) + multi-tile neg CTAs: each neg CTA
//       does 4 column-tiles with a continuously-pipelined 32-iteration loop
//       (no ring drain at tile boundaries; prologue churn /4; atomics /4).
// ---------------------------------------------------------------------------

#define DDIM 512
#define FP8_SCALE 32.0f

// fp8 matrices, TILED layout: [panel(128r)][kt(8)][r(128)][64B], swizzled chunks
__device__ __align__(1024) uint32_t g_Anq[(size_t)4096  * 128];
__device__ __align__(1024) uint32_t g_Pnq[(size_t)4096  * 128];
__device__ __align__(1024) uint32_t g_Nnq[(size_t)16384 * 128];
__device__ float    g_invA[4096];
__device__ float    g_invP[4096];
__device__ float    g_invN[16384];
__device__ float    g_S[4096];
__device__ int      g_done[64];      // per-64-row-panel neg completion counters
__device__ int      g_pos_done;
__device__ int      g_cs_done;
__device__ double   g_sum_loss;
__device__ double   g_cs[3][DDIM];

// ============================ PTX helpers ==================================
__device__ __forceinline__ uint32_t smem_to_u32(const void* p) {
    uint32_t a;
    asm("{ .reg .u64 t; cvta.to.shared.u64 t, %1; cvt.u32.u64 %0, t; }"
        : "=r"(a) : "l"(p));
    return a;
}
__device__ __forceinline__ void bulk_cp(uint32_t dst, const void* src,
                                        uint32_t bytes, uint32_t mbar) {
    asm volatile(
        "cp.async.bulk.shared::cta.global.mbarrier::complete_tx::bytes "
        "[%0], [%1], %2, [%3];"
        :: "r"(dst), "l"(src), "r"(bytes), "r"(mbar) : "memory");
}
#define MBARRIER_INIT(mbar, count) \
    asm volatile("mbarrier.init.shared.b64 [%0], %1;" \
        :: "r"((uint32_t)(mbar)), "r"((uint32_t)(count)) : "memory")
#define MBARRIER_EXPECT_TX(mbar, bytes) \
    asm volatile("mbarrier.arrive.expect_tx.shared.b64 _, [%0], %1;" \
        :: "r"((uint32_t)(mbar)), "r"((uint32_t)(bytes)) : "memory")
#define MBARRIER_WAIT_PARITY(mbar_smem_addr, phase_parity) do { \
    uint32_t _mbar = (uint32_t)(mbar_smem_addr); \
    uint32_t _parity = (uint32_t)(phase_parity); \
    uint32_t _done; \
    asm volatile( \
        "{\n\t.reg .pred p;\n\t" \
        "mbarrier.try_wait.parity.acquire.cta.shared::cta.b64 p, [%1], %2;\n\t" \
        "selp.b32 %0, 1, 0, p;\n\t}" \
        : "=r"(_done) : "r"(_mbar), "r"(_parity) : "memory"); \
    if (!_done) { \
        asm volatile( \
            "{\n\t.reg .pred P1;\n\t" \
            "WAIT_LOOP_%=:\n\t" \
            "mbarrier.try_wait.parity.acquire.cta.shared::cta.b64 P1, [%0], %1, 0x989680;\n\t" \
            "@P1 bra.uni WAIT_DONE_%=;\n\t" \
            "bra.uni WAIT_LOOP_%=;\n\t" \
            "WAIT_DONE_%=:\n\t}" \
            :: "r"(_mbar), "r"(_parity) : "memory"); \
    } \
} while (0)

__device__ __forceinline__ void ldsm_x4(uint32_t (&r)[4], uint32_t addr) {
    asm volatile("ldmatrix.sync.aligned.m8n8.x4.shared.b16 {%0,%1,%2,%3}, [%4];"
                 : "=r"(r[0]), "=r"(r[1]), "=r"(r[2]), "=r"(r[3]) : "r"(addr));
}
__device__ __forceinline__ void mma16832(float (&c)[4], const uint32_t (&a)[4],
                                         uint32_t b0, uint32_t b1) {
    asm volatile(
        "mma.sync.aligned.m16n8k32.row.col.f32.e4m3.e4m3.f32 "
        "{%0,%1,%2,%3}, {%4,%5,%6,%7}, {%8,%9}, {%0,%1,%2,%3};"
        : "+f"(c[0]), "+f"(c[1]), "+f"(c[2]), "+f"(c[3])
        : "r"(a[0]), "r"(a[1]), "r"(a[2]), "r"(a[3]), "r"(b0), "r"(b1));
}

// ====================== launch 1: normalize + zero =========================
#define NORM_BLOCKS 3072

__global__ void __launch_bounds__(256) normalize_kernel(const float* __restrict__ a,
                                                        const float* __restrict__ p,
                                                        const float* __restrict__ n) {
    if (blockIdx.x >= NORM_BLOCKS) {
        int i = (blockIdx.x - NORM_BLOCKS) * 256 + threadIdx.x;   // 0..4095
        g_S[i] = 0.0f;
        if (i < 3 * DDIM) ((double*)g_cs)[i] = 0.0;
        if (i < 64) g_done[i] = 0;
        if (i == 0) { g_sum_loss = 0.0; g_pos_done = 0; g_cs_done = 0; }
        return;
    }

    int rowBase;
    const float* in;
    uint32_t* outq;
    float* ginv;
    if (blockIdx.x < 512) {
        in = a; outq = g_Anq; ginv = g_invA; rowBase = blockIdx.x * 8;
    } else if (blockIdx.x < 1024) {
        in = p; outq = g_Pnq; ginv = g_invP; rowBase = (blockIdx.x - 512) * 8;
    } else {
        in = n; outq = g_Nnq; ginv = g_invN; rowBase = (blockIdx.x - 1024) * 8;
    }

    const int lane = threadIdx.x & 31;
    const int row = rowBase + (threadIdx.x >> 5);

    const float4* src = (const float4*)in + (size_t)row * (DDIM / 4);
    float4 v[4];
    #pragma unroll
    for (int i = 0; i < 4; i++) v[i] = src[lane + 32 * i];

    float ss = 0.0f;
    #pragma unroll
    for (int i = 0; i < 4; i++)
        ss += v[i].x * v[i].x + v[i].y * v[i].y + v[i].z * v[i].z + v[i].w * v[i].w;
    #pragma unroll
    for (int off = 16; off; off >>= 1)
        ss += __shfl_xor_sync(0xffffffffu, ss, off);

    float inv = 1.0f / fmaxf(sqrtf(ss), 1e-12f);
    if (lane == 0) ginv[row] = inv;

    const float sc = inv * FP8_SCALE;
    const uint32_t r = (uint32_t)row & 127;
    const uint32_t panel = (uint32_t)row >> 7;
    uint32_t* orow = outq + (size_t)panel * 16384 + r * 16;

    #pragma unroll
    for (int i = 0; i < 4; i++) {
        __nv_fp8x2_storage_t lo = __nv_cvt_float2_to_fp8x2(
            make_float2(v[i].x * sc, v[i].y * sc), __NV_SATFINITE, __NV_E4M3);
        __nv_fp8x2_storage_t hi = __nv_cvt_float2_to_fp8x2(
            make_float2(v[i].z * sc, v[i].w * sc), __NV_SATFINITE, __NV_E4M3);
        uint32_t packed = (uint32_t)lo | ((uint32_t)hi << 16);

        uint32_t t = (uint32_t)(lane + 32 * i);
        uint32_t kt = t >> 4;
        uint32_t cc = (t >> 2) & 3;
        uint32_t w = t & 3;
        uint32_t sw = cc ^ ((r >> 1) & 3);
        orow[kt * 2048 + sw * 4 + w] = packed;
    }
}

// ================= launch 2: GEMMs + colsum + finalize =====================
// CTA tile 64(M) x 128(N), warp tile 32x64, 128 threads, 4 CTAs/SM.
// bid [0,2048):       NEG  (panel64 = bid>>5, colGroup = bid&31; 4 col-tiles
//                          each, 32-iteration continuous pipeline)  B = g_Nnq
// bid [2048,4096):    POS  (panel64 = b2>>5,  col = b2&31; 1 tile)  B = g_Pnq
// bid [4096,4480):    COLSUM
// bid 4480:           FINALIZE
#define A_STAGE 4096
#define STAGE_BYTES 12288
#define NEG_CTAS 2048
#define NEG_TILES 4
#define NEG_ITERS (NEG_TILES * 8)
#define POS_CTAS 2048
#define GEMM_CTAS (NEG_CTAS + POS_CTAS)
#define CS_BLOCKS 384
#define FIN_BID (GEMM_CTAS + CS_BLOCKS)

__global__ void __launch_bounds__(128, 4) mma_fused_kernel(
        const float* __restrict__ inA, const float* __restrict__ inP,
        const float* __restrict__ inN, float* __restrict__ out,
        int B, int P, int N) {
    __shared__ __align__(128) char sbuf[3 * STAGE_BYTES];   // 36KB
    __shared__ __align__(8) uint64_t mbars[3];

    const int tid = threadIdx.x;
    const int bid = blockIdx.x;
    const int lane = tid & 31;
    const int warp = tid >> 5;

    // ---------------- finalize block ----------------
    if (bid == FIN_BID) {
        if (tid == 0) {
            while (((volatile int*)&g_pos_done)[0] < POS_CTAS ||
                   ((volatile int*)&g_cs_done)[0] < CS_BLOCKS)
                __nanosleep(128);
        }
        __syncthreads();
        __threadfence();

        double dAP = 0.0, dAN = 0.0;
        #pragma unroll
        for (int j = 0; j < 4; j++) {
            int col = tid + j * 128;
            double csA = __ldcg(&g_cs[0][col]);
            dAP += csA * __ldcg(&g_cs[1][col]);
            dAN += csA * __ldcg(&g_cs[2][col]);
        }
        #pragma unroll
        for (int off = 16; off; off >>= 1) {
            dAP += __shfl_xor_sync(0xffffffffu, dAP, off);
            dAN += __shfl_xor_sync(0xffffffffu, dAN, off);
        }
        __shared__ double rBs[4], rCs[4];
        if (lane == 0) { rBs[warp] = dAP; rCs[warp] = dAN; }
        __syncthreads();
        if (tid == 0) {
            double sAP = rBs[0] + rBs[1] + rBs[2] + rBs[3];
            double sAN = rCs[0] + rCs[1] + rCs[2] + rCs[3];
            const double T = 0.07;
            double bp = (double)B * (double)P;
            double bn = (double)B * (double)N;
            double mp = sAP / (bp * T);
            double mn = sAN / (bn * T);
            double tl = __ldcg(&g_sum_loss) / bp;
            out[0] = (float)tl;
            out[1] = (float)mp;
            out[2] = (float)mn;
            out[3] = (float)(mp - mn);
        }
        return;
    }

    // ---------------- colsum blocks ----------------
    if (bid >= GEMM_CTAS) {
        int b3 = bid - GEMM_CTAS;
        const float* in;
        const float* ginv;
        int m, base;
        if (b3 < 64)        { in = inA; ginv = g_invA; m = 0; base = b3 * 64; }
        else if (b3 < 128)  { in = inP; ginv = g_invP; m = 1; base = (b3 - 64) * 64; }
        else                { in = inN; ginv = g_invN; m = 2; base = (b3 - 128) * 64; }

        float acc[4] = {0.0f, 0.0f, 0.0f, 0.0f};
        for (int r = 0; r < 64; r++) {
            float iv = ginv[base + r];
            const float* rowp = in + (size_t)(base + r) * DDIM;
            #pragma unroll
            for (int j = 0; j < 4; j++)
                acc[j] += rowp[tid + j * 128] * iv;
        }
        #pragma unroll
        for (int j = 0; j < 4; j++)
            atomicAdd(&g_cs[m][tid + j * 128], (double)acc[j]);

        __syncthreads();
        if (tid == 0) {
            __threadfence();
            atomicAdd(&g_cs_done, 1);
        }
        return;
    }

    // ---------------- GEMM blocks ----------------
    const uint32_t sb = smem_to_u32(sbuf);
    const uint32_t mb = smem_to_u32(mbars);
    const int m0 = (warp >> 1) * 32;     // 0 or 32 within the 64-row tile
    const int n0 = (warp & 1) * 64;      // 0 or 64 within the 128-col tile

    const bool isNeg = (bid < NEG_CTAS);
    int rowPanel;
    const char* gB;                      // base of FIRST col tile
    int nIters;
    if (isNeg) {
        rowPanel = bid >> 5;
        int colGroup = bid & 31;         // 4 col-tiles each
        gB = (const char*)g_Nnq + (size_t)colGroup * NEG_TILES * 65536;
        nIters = NEG_ITERS;              // 32
    } else {
        int b2 = bid - NEG_CTAS;
        rowPanel = b2 >> 5;
        int colIdx = b2 & 31;
        gB = (const char*)g_Pnq + (size_t)colIdx * 65536;
        nIters = 8;
    }
    const int rowBase = rowPanel * 64;
    const char* gA = (const char*)g_Anq + (size_t)(rowPanel >> 1) * 65536
                     + (size_t)(rowPanel & 1) * 4096;

    float c[2][8][4];
    #pragma unroll
    for (int i = 0; i < 2; i++)
        #pragma unroll
        for (int j = 0; j < 8; j++)
            #pragma unroll
            for (int e = 0; e < 4; e++) c[i][j][e] = 0.0f;

    float rsAcc[2][2] = {{0.0f, 0.0f}, {0.0f, 0.0f}};   // neg rowsum accum
    const float invT = 1.0f / (0.07f * FP8_SCALE * FP8_SCALE);
    const int gID = lane >> 2;

    if (tid == 0) {
        #pragma unroll
        for (int s = 0; s < 3; s++) MBARRIER_INIT(mb + s * 8, 1);
    }
    __syncthreads();

    // prologue: iterations 0,1,2 into slots 0,1,2
    if (tid == 0) {
        #pragma unroll
        for (int s = 0; s < 3; s++) {
            MBARRIER_EXPECT_TX(mb + s * 8, STAGE_BYTES);
            bulk_cp(sb + s * STAGE_BYTES,           gA + (size_t)(s & 7) * 8192, 4096, mb + s * 8);
            bulk_cp(sb + s * STAGE_BYTES + A_STAGE,
                    gB + (size_t)(s >> 3) * 65536 + (size_t)(s & 7) * 8192, 8192, mb + s * 8);
        }
    }

    auto load_frags = [&](int slot, int ks, uint32_t (&a)[2][4], uint32_t (&b)[4][4]) {
        uint32_t aB = sb + slot * STAGE_BYTES;
        uint32_t bB = aB + A_STAGE;
        #pragma unroll
        for (int mf = 0; mf < 2; mf++) {
            uint32_t r = m0 + mf * 16 + (lane & 15);
            uint32_t cc = ks * 2 + (lane >> 4);
            uint32_t idx = r * 4 + (cc ^ ((r >> 1) & 3));
            ldsm_x4(a[mf], aB + idx * 16);
        }
        #pragma unroll
        for (int np = 0; np < 4; np++) {
            uint32_t grp = lane >> 3;
            uint32_t n = n0 + np * 16 + ((grp >> 1) ? 8 : 0) + (lane & 7);
            uint32_t cc = ks * 2 + (grp & 1);
            uint32_t idx = n * 4 + (cc ^ ((n >> 1) & 3));
            ldsm_x4(b[np], bB + idx * 16);
        }
    };
    auto mma_all = [&](const uint32_t (&a)[2][4], const uint32_t (&b)[4][4]) {
        #pragma unroll
        for (int mf = 0; mf < 2; mf++)
            #pragma unroll
            for (int nf = 0; nf < 8; nf++)
                mma16832(c[mf][nf], a[mf],
                         b[nf >> 1][(nf & 1) * 2], b[nf >> 1][(nf & 1) * 2 + 1]);
    };

    uint32_t a2[2][4], b2[4][4];

    for (int g = 0; g < nIters; g++) {
        int slot = g % 3;
        MBARRIER_WAIT_PARITY(mb + slot * 8, (g / 3) & 1);

        load_frags(slot, 0, a2, b2);
        mma_all(a2, b2);
        load_frags(slot, 1, a2, b2);
        mma_all(a2, b2);

        __syncthreads();
        if (tid == 0 && g + 3 < nIters) {
            int nt = g + 3;
            MBARRIER_EXPECT_TX(mb + slot * 8, STAGE_BYTES);
            bulk_cp(sb + slot * STAGE_BYTES,           gA + (size_t)(nt & 7) * 8192, 4096, mb + slot * 8);
            bulk_cp(sb + slot * STAGE_BYTES + A_STAGE,
                    gB + (size_t)(nt >> 3) * 65536 + (size_t)(nt & 7) * 8192, 8192, mb + slot * 8);
        }

        // neg: tile boundary mini-epilogue (exp-accumulate, reset c)
        if (isNeg && ((g & 7) == 7)) {
            #pragma unroll
            for (int mf = 0; mf < 2; mf++) {
                float rs0 = 0.0f, rs1 = 0.0f;
                #pragma unroll
                for (int nf = 0; nf < 8; nf++) {
                    rs0 += __expf(c[mf][nf][0] * invT) + __expf(c[mf][nf][1] * invT);
                    rs1 += __expf(c[mf][nf][2] * invT) + __expf(c[mf][nf][3] * invT);
                    c[mf][nf][0] = 0.0f; c[mf][nf][1] = 0.0f;
                    c[mf][nf][2] = 0.0f; c[mf][nf][3] = 0.0f;
                }
                rsAcc[mf][0] += rs0;
                rsAcc[mf][1] += rs1;
            }
        }
    }

    // ---- final epilogues ----
    if (isNeg) {
        #pragma unroll
        for (int mf = 0; mf < 2; mf++) {
            float rs0 = rsAcc[mf][0], rs1 = rsAcc[mf][1];
            rs0 += __shfl_xor_sync(0xffffffffu, rs0, 1);
            rs0 += __shfl_xor_sync(0xffffffffu, rs0, 2);
            rs1 += __shfl_xor_sync(0xffffffffu, rs1, 1);
            rs1 += __shfl_xor_sync(0xffffffffu, rs1, 2);
            if ((lane & 3) == 0) {
                int row = rowBase + m0 + mf * 16 + gID;
                atomicAdd(&g_S[row], rs0);
                atomicAdd(&g_S[row + 8], rs1);
            }
        }
        __syncthreads();
        if (tid == 0) {
            __threadfence();
            atomicAdd(&g_done[rowPanel], 1);
        }
    } else {
        if (tid == 0) {
            while (((volatile int*)g_done)[rowPanel] < 32)
                __nanosleep(64);
        }
        __syncthreads();
        __threadfence();

        float lsum = 0.0f;
        #pragma unroll
        for (int mf = 0; mf < 2; mf++) {
            int row = rowBase + m0 + mf * 16 + gID;
            float S0 = __ldcg(&g_S[row]);
            float S1 = __ldcg(&g_S[row + 8]);
            #pragma unroll
            for (int nf = 0; nf < 8; nf++) {
                float p0 = __expf(c[mf][nf][0] * invT);
                float p1 = __expf(c[mf][nf][1] * invT);
                float p2 = __expf(c[mf][nf][2] * invT);
                float p3 = __expf(c[mf][nf][3] * invT);
                lsum += __logf(__fdividef(p0, p0 + S0) + 1e-8f);
                lsum += __logf(__fdividef(p1, p1 + S0) + 1e-8f);
                lsum += __logf(__fdividef(p2, p2 + S1) + 1e-8f);
                lsum += __logf(__fdividef(p3, p3 + S1) + 1e-8f);
            }
        }
        double acc = -(double)lsum;
        #pragma unroll
        for (int off = 16; off; off >>= 1)
            acc += __shfl_xor_sync(0xffffffffu, acc, off);
        __shared__ double red[4];
        if (lane == 0) red[warp] = acc;
        __syncthreads();
        if (tid == 0) {
            atomicAdd(&g_sum_loss, red[0] + red[1] + red[2] + red[3]);
            __threadfence();
            atomicAdd(&g_pos_done, 1);
        }
    }
}

// ============================ launch =======================================
extern "C" void kernel_launch(void* const* d_in, const int* in_sizes, int n_in,
                              void* d_out, int out_size) {
    const float* a = (const float*)d_in[0];
    const float* p = (const float*)d_in[1];
    const float* n = (const float*)d_in[2];
    int B = in_sizes[0] / DDIM;   // 4096
    int P = in_sizes[1] / DDIM;   // 4096
    int N = in_sizes[2] / DDIM;   // 16384

    normalize_kernel<<<NORM_BLOCKS + 16, 256>>>(a, p, n);
    mma_fused_kernel<<<FIN_BID + 1, 128>>>(a, p, n, (float*)d_out, B, P, N);
}